// round 1
// baseline (speedup 1.0000x reference)
#include <cuda_runtime.h>
#include <math.h>

#define NN 50000
#define EE 800000
#define DD 64
#define TT 8
#define RR 8
#define NB_SCAN 196   // ceil(NN/256)

// ---------------- scratch (static device memory; no allocations) ----------------
__device__ int   g_is64_adj, g_is64_et, g_is64_nt;
__device__ float g_Wk[TT*RR*DD*DD];           // 1 MB
__device__ float g_Wv[TT*RR*DD*DD];           // 1 MB
__device__ float g_krel[(size_t)NN*RR*DD];    // 102.4 MB  [n][r][j]
__device__ float g_vrel[(size_t)NN*RR*DD];    // 102.4 MB
__device__ float g_qnode[NN*DD];              // 12.8 MB
__device__ float g_agg[NN*DD];                // 12.8 MB
__device__ int   g_perm[NN];
__device__ int   g_deg[NN];
__device__ int   g_cursor[NN];
__device__ int   g_rowptr[NN+1];
__device__ int   g_bsum[256];
__device__ int   g_boff[256];
__device__ int   g_tcount[TT];
__device__ int   g_tbase[TT];
__device__ int   g_tcur[TT];
__device__ int   g_csr[EE];                   // src | (r<<20)

__device__ __forceinline__ int ld_idx(const void* p, long i, int is64) {
    if (is64) return (int)(((const long long*)p)[i]);
    return ((const int*)p)[i];
}

// ---------------- dtype detection: int64 arrays have zero high words ----------------
__global__ void k_detect(const void* adj, const void* et, const void* nt) {
    if (threadIdx.x != 0 || blockIdx.x != 0) return;
    int a = 1, b = 1, c = 1;
    for (int i = 0; i < 128; i++) if (((const int*)adj)[2*(i*1000)+1]) { a = 0; break; }
    for (int i = 0; i < 128; i++) if (((const int*)et )[2*(i*3000)+1]) { b = 0; break; }
    for (int i = 0; i < 128; i++) if (((const int*)nt )[2*(i*150 )+1]) { c = 0; break; }
    g_is64_adj = a; g_is64_et = b; g_is64_nt = c;
}

__global__ void k_zero() {
    int i = blockIdx.x*blockDim.x + threadIdx.x;
    if (i < NN) { g_deg[i] = 0; g_cursor[i] = 0; }
    if (i < TT) { g_tcount[i] = 0; g_tcur[i] = 0; }
    if (i == 0) g_rowptr[NN] = EE;
}

// ---------------- node counting sort by type ----------------
__global__ void k_nhist(const void* nt) {
    int i = blockIdx.x*blockDim.x + threadIdx.x;
    if (i >= NN) return;
    atomicAdd(&g_tcount[ld_idx(nt, i, g_is64_nt)], 1);
}
__global__ void k_tscan() {
    if (threadIdx.x == 0 && blockIdx.x == 0) {
        int s = 0;
        for (int t = 0; t < TT; t++) { g_tbase[t] = s; s += g_tcount[t]; }
    }
}
__global__ void k_nscatter(const void* nt) {
    int i = blockIdx.x*blockDim.x + threadIdx.x;
    if (i >= NN) return;
    int t = ld_idx(nt, i, g_is64_nt);
    int p = g_tbase[t] + atomicAdd(&g_tcur[t], 1);
    g_perm[p] = i;
}

// ---------------- CSR build over dst ----------------
__global__ void k_ehist(const void* adj) {
    int e = blockIdx.x*blockDim.x + threadIdx.x;
    if (e >= EE) return;
    int d = ld_idx(adj, (long)EE + e, g_is64_adj);
    atomicAdd(&g_deg[d], 1);
}
__global__ void k_scanA() {
    __shared__ int s[256];
    int i = blockIdx.x*256 + threadIdx.x;
    int v = (i < NN) ? g_deg[i] : 0;
    s[threadIdx.x] = v; __syncthreads();
    for (int off = 1; off < 256; off <<= 1) {
        int t = (threadIdx.x >= off) ? s[threadIdx.x - off] : 0;
        __syncthreads();
        s[threadIdx.x] += t;
        __syncthreads();
    }
    if (i < NN) g_rowptr[i] = s[threadIdx.x] - v;
    if (threadIdx.x == 255) g_bsum[blockIdx.x] = s[255];
}
__global__ void k_scanB() {
    __shared__ int s[256];
    int i = threadIdx.x;
    int v = (i < NB_SCAN) ? g_bsum[i] : 0;
    s[i] = v; __syncthreads();
    for (int off = 1; off < 256; off <<= 1) {
        int t = (i >= off) ? s[i - off] : 0;
        __syncthreads();
        s[i] += t;
        __syncthreads();
    }
    g_boff[i] = s[i] - v;
}
__global__ void k_scanC() {
    int i = blockIdx.x*256 + threadIdx.x;
    if (i < NN) g_rowptr[i] += g_boff[blockIdx.x];
}
__global__ void k_escatter(const void* adj, const void* et) {
    int e = blockIdx.x*blockDim.x + threadIdx.x;
    if (e >= EE) return;
    int sflag = g_is64_adj;
    int src = ld_idx(adj, e, sflag);
    int dst = ld_idx(adj, (long)EE + e, sflag);
    int r   = ld_idx(et, e, g_is64_et);
    int p = g_rowptr[dst] + atomicAdd(&g_cursor[dst], 1);
    g_csr[p] = src | (r << 20);
}

// ---------------- combined weights: Wk[t][r] = kw[t]@att[r]; Wv[t][r]=vw[t]@msg[r] ----------------
__global__ void k_wcomb(const float* __restrict__ kw, const float* __restrict__ att,
                        const float* __restrict__ vw, const float* __restrict__ msg) {
    __shared__ float As[64*64];
    __shared__ float Bs[64*64];
    int bid = blockIdx.x;  // 0..127
    const float *A, *B; float* O;
    if (bid < 64) { int t = bid >> 3, r = bid & 7; A = kw + t*4096; B = att + r*4096; O = g_Wk + bid*4096; }
    else { int q = bid - 64; int t = q >> 3, r = q & 7; A = vw + t*4096; B = msg + r*4096; O = g_Wv + q*4096; }
    for (int i = threadIdx.x; i < 4096; i += 256) { As[i] = A[i]; Bs[i] = B[i]; }
    __syncthreads();
    int j  = threadIdx.x & 63;
    int i0 = (threadIdx.x >> 6) * 16;
    float acc[16];
    #pragma unroll
    for (int ii = 0; ii < 16; ii++) acc[ii] = 0.f;
    for (int k = 0; k < 64; k++) {
        float b = Bs[k*64 + j];
        #pragma unroll
        for (int ii = 0; ii < 16; ii++) acc[ii] += As[(i0+ii)*64 + k] * b;
    }
    #pragma unroll
    for (int ii = 0; ii < 16; ii++) O[(i0+ii)*64 + j] = acc[ii];
}

// ---------------- typed projection GEMM: out[node] = src[node] @ W[type(node)] ----------------
// 512 threads, 128 nodes/tile (sorted by type), warp = 8 nodes x 64 cols register-blocked.
__global__ void k_proj(const float* __restrict__ src,
                       const float* __restrict__ Wbase, int tstride,
                       float* __restrict__ outb, int ostride,
                       const void* nt, const float* __restrict__ skipv) {
    extern __shared__ float sm[];
    float* sW = sm;                       // 8*4096 floats
    float* sH = sm + 8*4096;              // 128*64 floats
    int* sNode = (int*)(sH + 128*64);     // 128
    int* sType = sNode + 128;             // 128
    int* sMask = sType + 128;             // 1
    int tid = threadIdx.x;
    if (tid == 0) *sMask = 0;
    __syncthreads();
    int tilebase = blockIdx.x * 128;
    if (tid < 128) {
        int idx = tilebase + tid;
        int cidx = (idx < NN) ? idx : (NN - 1);
        int node = g_perm[cidx];
        sNode[tid] = node;
        int t = ld_idx(nt, node, g_is64_nt);
        sType[tid] = t;
        atomicOr(sMask, 1 << t);
    }
    __syncthreads();
    int mask = *sMask;
    for (int e = tid; e < 128*64; e += 512)
        sH[e] = src[(long)sNode[e >> 6]*64 + (e & 63)];
    for (int t = 0; t < 8; t++) {
        if (mask & (1 << t)) {
            const float4* wsrc = (const float4*)(Wbase + (long)t * tstride);
            float4* wdst = (float4*)(sW + t*4096);
            for (int e = tid; e < 1024; e += 512) wdst[e] = wsrc[e];
        }
    }
    __syncthreads();

    int w = tid >> 5, lane = tid & 31;
    int ib = w * 8;
    int ty[8]; bool uni = true;
    #pragma unroll
    for (int i = 0; i < 8; i++) { ty[i] = sType[ib + i]; uni &= (ty[i] == ty[0]); }
    float2 acc[8];
    #pragma unroll
    for (int i = 0; i < 8; i++) acc[i] = make_float2(0.f, 0.f);

    if (uni) {
        const float* Wp = sW + ty[0]*4096 + lane*2;
        const float* Hp = sH + ib*64;
        #pragma unroll 4
        for (int k = 0; k < 64; k += 2) {
            float2 wa = *(const float2*)(Wp + k*64);
            float2 wb = *(const float2*)(Wp + (k+1)*64);
            #pragma unroll
            for (int i = 0; i < 8; i++) {
                float2 hv = *(const float2*)(Hp + i*64 + k);
                acc[i].x += hv.x*wa.x + hv.y*wb.x;
                acc[i].y += hv.x*wa.y + hv.y*wb.y;
            }
        }
    } else {
        for (int k = 0; k < 64; k++) {
            #pragma unroll
            for (int i = 0; i < 8; i++) {
                float2 wv = *(const float2*)(sW + ty[i]*4096 + k*64 + lane*2);
                float hv = sH[(ib+i)*64 + k];
                acc[i].x += hv*wv.x;
                acc[i].y += hv*wv.y;
            }
        }
    }
    #pragma unroll
    for (int i = 0; i < 8; i++) {
        int idx = tilebase + ib + i;
        if (idx < NN) {
            int node = sNode[ib + i];
            float sc = 1.0f;
            if (skipv) { float sk = skipv[ty[i]]; sc = 1.0f / (1.0f + __expf(-sk)); }
            *(float2*)(outb + (long)node*ostride + lane*2) =
                make_float2(acc[i].x*sc, acc[i].y*sc);
        }
    }
}

// ---------------- fused edge phase: per-dst warp, online softmax, register accumulate ----------------
__global__ void k_edge(const float* __restrict__ pri) {
    __shared__ float spri[8];
    if (threadIdx.x < 8) spri[threadIdx.x] = pri[threadIdx.x];
    __syncthreads();
    int d = blockIdx.x*8 + (threadIdx.x >> 5);
    if (d >= NN) return;
    int lane = threadIdx.x & 31;
    float2 q = *(const float2*)&g_qnode[d*64 + lane*2];
    int rs = g_rowptr[d], re = g_rowptr[d+1];
    float m = -3.0e38f, s = 0.f;
    float2 acc = make_float2(0.f, 0.f);
    for (int p = rs; p < re; p++) {
        int pk = g_csr[p];
        int src = pk & 0xFFFFF;
        int r   = pk >> 20;
        float2 kv = *(const float2*)(g_krel + (long)src*512 + r*64 + lane*2);
        float part = q.x*kv.x + q.y*kv.y;
        part += __shfl_xor_sync(0xFFFFFFFFu, part, 16);
        part += __shfl_xor_sync(0xFFFFFFFFu, part, 8);
        part += __shfl_xor_sync(0xFFFFFFFFu, part, 4);
        part += __shfl_xor_sync(0xFFFFFFFFu, part, 2);
        part += __shfl_xor_sync(0xFFFFFFFFu, part, 1);
        float score = part * spri[r] * 0.125f;
        float mn = fmaxf(m, score);
        float c = __expf(m - mn);
        float wgt = __expf(score - mn);
        float2 vv = *(const float2*)(g_vrel + (long)src*512 + r*64 + lane*2);
        s = s*c + wgt;
        acc.x = acc.x*c + wgt*vv.x;
        acc.y = acc.y*c + wgt*vv.y;
        m = mn;
    }
    float inv = 1.0f / (s + 1e-16f);
    *(float2*)&g_agg[d*64 + lane*2] = make_float2(acc.x*inv, acc.y*inv);
}

// ---------------- launch ----------------
extern "C" void kernel_launch(void* const* d_in, const int* in_sizes, int n_in,
                              void* d_out, int out_size) {
    const float* h   = (const float*)d_in[0];
    const void*  adj = d_in[1];
    const void*  et  = d_in[2];
    const void*  nt  = d_in[3];
    int off = n_in - 8;  // trailing 8 args regardless of scalar src/dst_type presence
    const float* kw   = (const float*)d_in[off + 0];
    const float* qw   = (const float*)d_in[off + 1];
    const float* vw   = (const float*)d_in[off + 2];
    const float* aw   = (const float*)d_in[off + 3];
    const float* pri  = (const float*)d_in[off + 4];
    const float* att  = (const float*)d_in[off + 5];
    const float* msg  = (const float*)d_in[off + 6];
    const float* skip = (const float*)d_in[off + 7];
    float* out = (float*)d_out;

    const int PROJ_SMEM = (8*4096 + 128*64)*4 + 128*4*2 + 16;
    cudaFuncSetAttribute(k_proj, cudaFuncAttributeMaxDynamicSharedMemorySize, PROJ_SMEM);

    float *dWk, *dWv, *dKrel, *dVrel, *dQ, *dAgg;
    cudaGetSymbolAddress((void**)&dWk,   g_Wk);
    cudaGetSymbolAddress((void**)&dWv,   g_Wv);
    cudaGetSymbolAddress((void**)&dKrel, g_krel);
    cudaGetSymbolAddress((void**)&dVrel, g_vrel);
    cudaGetSymbolAddress((void**)&dQ,    g_qnode);
    cudaGetSymbolAddress((void**)&dAgg,  g_agg);

    k_detect<<<1, 1>>>(adj, et, nt);
    k_zero<<<(NN + 255)/256, 256>>>();
    k_nhist<<<(NN + 255)/256, 256>>>(nt);
    k_tscan<<<1, 1>>>();
    k_nscatter<<<(NN + 255)/256, 256>>>(nt);
    k_ehist<<<(EE + 255)/256, 256>>>(adj);
    k_scanA<<<NB_SCAN, 256>>>();
    k_scanB<<<1, 256>>>();
    k_scanC<<<NB_SCAN, 256>>>();
    k_escatter<<<(EE + 255)/256, 256>>>(adj, et);
    k_wcomb<<<128, 256>>>(kw, att, vw, msg);

    int nb = (NN + 127) / 128;
    for (int r = 0; r < 8; r++)
        k_proj<<<nb, 512, PROJ_SMEM>>>(h, dWk + r*4096, 8*4096, dKrel + r*64, 512, nt, nullptr);
    for (int r = 0; r < 8; r++)
        k_proj<<<nb, 512, PROJ_SMEM>>>(h, dWv + r*4096, 8*4096, dVrel + r*64, 512, nt, nullptr);
    k_proj<<<nb, 512, PROJ_SMEM>>>(h, qw, 4096, dQ, 64, nt, nullptr);

    k_edge<<<(NN + 7)/8, 256>>>(pri);

    k_proj<<<nb, 512, PROJ_SMEM>>>(dAgg, aw, 4096, out, 64, nt, skip);
}

// round 2
// speedup vs baseline: 1.4386x; 1.4386x over previous
#include <cuda_runtime.h>
#include <math.h>

#define NN 50000
#define EE 800000
#define TT 8
#define RR 8
#define NB_SCAN 196   // ceil(NN/256)

// ---------------- scratch (static device memory; no allocations) ----------------
__device__ int   g_is64_adj, g_is64_et, g_is64_nt;
__device__ float g_Wqa[TT*64*512];              // 1 MB: Wq[t] @ A_r^T, r-concat
__device__ float g_Wma[TT*512*64];              // 1 MB: Mstack @ Wa[t]
__device__ float g_knode[(size_t)NN*64];        // 12.8 MB (permuted order)
__device__ float g_vnode[(size_t)NN*64];        // 12.8 MB (permuted order)
__device__ float g_qrel[(size_t)NN*512];        // 102.4 MB (permuted order)
__device__ float g_bucket[(size_t)NN*512];      // 102.4 MB (permuted order)
__device__ int   g_perm[NN];
__device__ int   g_iperm[NN];
__device__ int   g_deg[NN];
__device__ int   g_cursor[NN];
__device__ int   g_rowptr[NN+1];
__device__ int   g_bsum[256];
__device__ int   g_boff[256];
__device__ int   g_tcount[TT];
__device__ int   g_tbase[TT];
__device__ int   g_tcur[TT];
__device__ int   g_csr[EE];                     // src_pos | (r<<20)

__device__ __forceinline__ int ld_idx(const void* p, long i, int is64) {
    if (is64) return (int)(((const long long*)p)[i]);
    return ((const int*)p)[i];
}

// ---------------- dtype detection ----------------
__global__ void k_detect(const void* adj, const void* et, const void* nt) {
    if (threadIdx.x != 0 || blockIdx.x != 0) return;
    int a = 1, b = 1, c = 1;
    for (int i = 0; i < 128; i++) if (((const int*)adj)[2*(i*1000)+1]) { a = 0; break; }
    for (int i = 0; i < 128; i++) if (((const int*)et )[2*(i*3000)+1]) { b = 0; break; }
    for (int i = 0; i < 128; i++) if (((const int*)nt )[2*(i*150 )+1]) { c = 0; break; }
    g_is64_adj = a; g_is64_et = b; g_is64_nt = c;
}

__global__ void k_zero() {
    int i = blockIdx.x*blockDim.x + threadIdx.x;
    if (i < NN) { g_deg[i] = 0; g_cursor[i] = 0; }
    if (i < TT) { g_tcount[i] = 0; g_tcur[i] = 0; }
    if (i == 0) g_rowptr[NN] = EE;
}

// ---------------- node counting sort by type ----------------
__global__ void k_nhist(const void* nt) {
    int i = blockIdx.x*blockDim.x + threadIdx.x;
    if (i >= NN) return;
    atomicAdd(&g_tcount[ld_idx(nt, i, g_is64_nt)], 1);
}
__global__ void k_tscan() {
    if (threadIdx.x == 0 && blockIdx.x == 0) {
        int s = 0;
        for (int t = 0; t < TT; t++) { g_tbase[t] = s; s += g_tcount[t]; }
    }
}
__global__ void k_nscatter(const void* nt) {
    int i = blockIdx.x*blockDim.x + threadIdx.x;
    if (i >= NN) return;
    int t = ld_idx(nt, i, g_is64_nt);
    int p = g_tbase[t] + atomicAdd(&g_tcur[t], 1);
    g_perm[p] = i;
}
__global__ void k_iperm() {
    int i = blockIdx.x*blockDim.x + threadIdx.x;
    if (i >= NN) return;
    g_iperm[g_perm[i]] = i;
}

// ---------------- CSR build over permuted dst ----------------
__global__ void k_ehist(const void* adj) {
    int e = blockIdx.x*blockDim.x + threadIdx.x;
    if (e >= EE) return;
    int d = ld_idx(adj, (long)EE + e, g_is64_adj);
    atomicAdd(&g_deg[g_iperm[d]], 1);
}
__global__ void k_scanA() {
    __shared__ int s[256];
    int i = blockIdx.x*256 + threadIdx.x;
    int v = (i < NN) ? g_deg[i] : 0;
    s[threadIdx.x] = v; __syncthreads();
    for (int off = 1; off < 256; off <<= 1) {
        int t = (threadIdx.x >= off) ? s[threadIdx.x - off] : 0;
        __syncthreads();
        s[threadIdx.x] += t;
        __syncthreads();
    }
    if (i < NN) g_rowptr[i] = s[threadIdx.x] - v;
    if (threadIdx.x == 255) g_bsum[blockIdx.x] = s[255];
}
__global__ void k_scanB() {
    __shared__ int s[256];
    int i = threadIdx.x;
    int v = (i < NB_SCAN) ? g_bsum[i] : 0;
    s[i] = v; __syncthreads();
    for (int off = 1; off < 256; off <<= 1) {
        int t = (i >= off) ? s[i - off] : 0;
        __syncthreads();
        s[i] += t;
        __syncthreads();
    }
    g_boff[i] = s[i] - v;
}
__global__ void k_scanC() {
    int i = blockIdx.x*256 + threadIdx.x;
    if (i < NN) g_rowptr[i] += g_boff[blockIdx.x];
}
__global__ void k_escatter(const void* adj, const void* et) {
    int e = blockIdx.x*blockDim.x + threadIdx.x;
    if (e >= EE) return;
    int sflag = g_is64_adj;
    int src = ld_idx(adj, e, sflag);
    int dst = ld_idx(adj, (long)EE + e, sflag);
    int r   = ld_idx(et, e, g_is64_et);
    int dp = g_iperm[dst];
    int sp = g_iperm[src];
    int p = g_rowptr[dp] + atomicAdd(&g_cursor[dp], 1);
    g_csr[p] = sp | (r << 20);
}

// ---------------- weight folds ----------------
// Wqa[t][m][r*64+i] = sum_j qw[t][m][j] * att[r][i][j]
__global__ void k_fold_qa(const float* __restrict__ qw, const float* __restrict__ att) {
    __shared__ float sQ[4096], sT[4096];
    int b = blockIdx.x; int t = b >> 3, r = b & 7;
    int tid = threadIdx.x;
    for (int e = tid; e < 1024; e += 256) {
        ((float4*)sQ)[e] = ((const float4*)(qw + t*4096))[e];
        ((float4*)sT)[e] = ((const float4*)(att + r*4096))[e];
    }
    __syncthreads();
    int i = tid & 63, mg = (tid >> 6) * 16;
    float acc[16];
    #pragma unroll
    for (int u = 0; u < 16; u++) acc[u] = 0.f;
    for (int j = 0; j < 64; j++) {
        float bv = sT[i*64 + j];
        #pragma unroll
        for (int u = 0; u < 16; u++) acc[u] += sQ[(mg+u)*64 + j] * bv;
    }
    #pragma unroll
    for (int u = 0; u < 16; u++)
        g_Wqa[t*32768 + (mg+u)*512 + r*64 + i] = acc[u];
}
// Wma[t][r*64+i][j] = sum_c msg[r][i][c] * aw[t][c][j]
__global__ void k_fold_ma(const float* __restrict__ msg, const float* __restrict__ aw) {
    __shared__ float sM[4096], sW[4096];
    int b = blockIdx.x; int t = b >> 3, r = b & 7;
    int tid = threadIdx.x;
    for (int e = tid; e < 1024; e += 256) {
        ((float4*)sM)[e] = ((const float4*)(msg + r*4096))[e];
        ((float4*)sW)[e] = ((const float4*)(aw + t*4096))[e];
    }
    __syncthreads();
    int j = tid & 63, ig = (tid >> 6) * 16;
    float acc[16];
    #pragma unroll
    for (int u = 0; u < 16; u++) acc[u] = 0.f;
    for (int c = 0; c < 64; c++) {
        float bv = sW[c*64 + j];
        #pragma unroll
        for (int u = 0; u < 16; u++) acc[u] += sM[(ig+u)*64 + c] * bv;
    }
    #pragma unroll
    for (int u = 0; u < 16; u++)
        g_Wma[t*32768 + (r*64 + ig+u)*64 + j] = acc[u];
}

// ---------------- k_node/v_node typed GEMM: 128 nodes x 64 cols, tile 8x4 ----------------
__global__ void k_kv(const float* __restrict__ h, const float* __restrict__ kw,
                     const float* __restrict__ vw, const void* nt) {
    extern __shared__ float sm[];
    float* sA  = sm;            // 64*128 (h transposed)
    float* sWk = sA + 8192;     // 4096
    float* sWv = sWk + 4096;    // 4096
    int* sNode = (int*)(sWv + 4096);
    int* sTy   = sNode + 128;
    int tid = threadIdx.x;
    int base = blockIdx.x * 128;
    if (tid < 128) {
        int idx = base + tid; if (idx > NN-1) idx = NN-1;
        int node = g_perm[idx];
        sNode[tid] = node;
        sTy[tid] = ld_idx(nt, node, g_is64_nt);
    }
    __syncthreads();
    {
        int m = tid >> 1, half = tid & 1;
        const float4* hp = (const float4*)(h + (size_t)sNode[m]*64 + half*32);
        #pragma unroll
        for (int j = 0; j < 8; j++) {
            float4 v = hp[j];
            int k0 = half*32 + j*4;
            sA[(k0+0)*128 + m] = v.x;
            sA[(k0+1)*128 + m] = v.y;
            sA[(k0+2)*128 + m] = v.z;
            sA[(k0+3)*128 + m] = v.w;
        }
    }
    __syncthreads();
    int t0 = sTy[0], t1 = sTy[127];
    int wy = tid >> 4, wx = tid & 15;
    int m0 = wy*8, c0 = wx*4;
    for (int t = t0; t <= t1; t++) {
        for (int e = tid; e < 1024; e += 256) {
            ((float4*)sWk)[e] = ((const float4*)(kw + t*4096))[e];
            ((float4*)sWv)[e] = ((const float4*)(vw + t*4096))[e];
        }
        __syncthreads();
        float aK[8][4], aV[8][4];
        #pragma unroll
        for (int i = 0; i < 8; i++)
            #pragma unroll
            for (int j = 0; j < 4; j++) { aK[i][j] = 0.f; aV[i][j] = 0.f; }
        #pragma unroll 4
        for (int k = 0; k < 64; k++) {
            float4 bk = *(const float4*)&sWk[k*64 + c0];
            float4 bv = *(const float4*)&sWv[k*64 + c0];
            float4 a0 = *(const float4*)&sA[k*128 + m0];
            float4 a1 = *(const float4*)&sA[k*128 + m0 + 4];
            float av[8] = {a0.x,a0.y,a0.z,a0.w,a1.x,a1.y,a1.z,a1.w};
            #pragma unroll
            for (int i = 0; i < 8; i++) {
                aK[i][0] += av[i]*bk.x; aK[i][1] += av[i]*bk.y;
                aK[i][2] += av[i]*bk.z; aK[i][3] += av[i]*bk.w;
                aV[i][0] += av[i]*bv.x; aV[i][1] += av[i]*bv.y;
                aV[i][2] += av[i]*bv.z; aV[i][3] += av[i]*bv.w;
            }
        }
        #pragma unroll
        for (int i = 0; i < 8; i++) {
            int row = m0 + i, idx = base + row;
            if (idx < NN && sTy[row] == t) {
                *(float4*)&g_knode[(size_t)idx*64 + c0] = make_float4(aK[i][0],aK[i][1],aK[i][2],aK[i][3]);
                *(float4*)&g_vnode[(size_t)idx*64 + c0] = make_float4(aV[i][0],aV[i][1],aV[i][2],aV[i][3]);
            }
        }
        __syncthreads();
    }
}

// ---------------- q_rel GEMM: out[pos][512] = h[perm] @ Wqa[t]; 128x128 tiles, 8x8 ----------------
__global__ void k_qrel(const float* __restrict__ h, const void* nt) {
    extern __shared__ float sm[];
    float* sA = sm;            // 64*128 (h transposed)
    float* sB = sA + 8192;     // 64*128 (W slice)
    int* sNode = (int*)(sB + 8192);
    int* sTy   = sNode + 128;
    int tid = threadIdx.x;
    int base = blockIdx.x * 128;
    int col0 = blockIdx.y * 128;
    if (tid < 128) {
        int idx = base + tid; if (idx > NN-1) idx = NN-1;
        int node = g_perm[idx];
        sNode[tid] = node;
        sTy[tid] = ld_idx(nt, node, g_is64_nt);
    }
    __syncthreads();
    {
        int m = tid >> 1, half = tid & 1;
        const float4* hp = (const float4*)(h + (size_t)sNode[m]*64 + half*32);
        #pragma unroll
        for (int j = 0; j < 8; j++) {
            float4 v = hp[j];
            int k0 = half*32 + j*4;
            sA[(k0+0)*128 + m] = v.x;
            sA[(k0+1)*128 + m] = v.y;
            sA[(k0+2)*128 + m] = v.z;
            sA[(k0+3)*128 + m] = v.w;
        }
    }
    __syncthreads();
    int t0 = sTy[0], t1 = sTy[127];
    int wy = tid >> 4, wx = tid & 15;
    int m0 = wy*8, n0 = wx*8;
    for (int t = t0; t <= t1; t++) {
        for (int e = tid; e < 2048; e += 256) {
            int k = e >> 5, n4 = e & 31;
            ((float4*)&sB[k*128])[n4] = *(const float4*)&g_Wqa[t*32768 + k*512 + col0 + n4*4];
        }
        __syncthreads();
        float acc[8][8];
        #pragma unroll
        for (int i = 0; i < 8; i++)
            #pragma unroll
            for (int j = 0; j < 8; j++) acc[i][j] = 0.f;
        #pragma unroll 2
        for (int k = 0; k < 64; k++) {
            float4 a0 = *(const float4*)&sA[k*128 + m0];
            float4 a1 = *(const float4*)&sA[k*128 + m0 + 4];
            float4 b0 = *(const float4*)&sB[k*128 + n0];
            float4 b1 = *(const float4*)&sB[k*128 + n0 + 4];
            float av[8] = {a0.x,a0.y,a0.z,a0.w,a1.x,a1.y,a1.z,a1.w};
            float bv[8] = {b0.x,b0.y,b0.z,b0.w,b1.x,b1.y,b1.z,b1.w};
            #pragma unroll
            for (int i = 0; i < 8; i++)
                #pragma unroll
                for (int j = 0; j < 8; j++) acc[i][j] += av[i]*bv[j];
        }
        #pragma unroll
        for (int i = 0; i < 8; i++) {
            int row = m0 + i, idx = base + row;
            if (idx < NN && sTy[row] == t) {
                *(float4*)&g_qrel[(size_t)idx*512 + col0 + n0]     = make_float4(acc[i][0],acc[i][1],acc[i][2],acc[i][3]);
                *(float4*)&g_qrel[(size_t)idx*512 + col0 + n0 + 4] = make_float4(acc[i][4],acc[i][5],acc[i][6],acc[i][7]);
            }
        }
        __syncthreads();
    }
}

// ---------------- fused edge phase: warp per dst, online softmax, reg buckets ----------------
__global__ void k_edge(const float* __restrict__ pri) {
    int d = blockIdx.x*8 + (threadIdx.x >> 5);
    if (d >= NN) return;
    int lane = threadIdx.x & 31;
    float2 q[8];
    float pr[8];
    #pragma unroll
    for (int r = 0; r < 8; r++) {
        q[r] = *(const float2*)&g_qrel[(size_t)d*512 + r*64 + lane*2];
        pr[r] = pri[r] * 0.125f;
    }
    int rs = g_rowptr[d], re = g_rowptr[d+1];
    float m = -3.0e38f, s = 0.f;
    float2 b[8];
    #pragma unroll
    for (int r = 0; r < 8; r++) b[r] = make_float2(0.f, 0.f);
    for (int p = rs; p < re; p++) {
        int pk = g_csr[p];
        int sp = pk & 0xFFFFF;
        int r  = pk >> 20;
        float2 kv = *(const float2*)&g_knode[(size_t)sp*64 + lane*2];
        float2 qs = q[0]; float prs = pr[0];
        #pragma unroll
        for (int rr = 1; rr < 8; rr++) if (r == rr) { qs = q[rr]; prs = pr[rr]; }
        float part = kv.x*qs.x + kv.y*qs.y;
        part += __shfl_xor_sync(0xFFFFFFFFu, part, 16);
        part += __shfl_xor_sync(0xFFFFFFFFu, part, 8);
        part += __shfl_xor_sync(0xFFFFFFFFu, part, 4);
        part += __shfl_xor_sync(0xFFFFFFFFu, part, 2);
        part += __shfl_xor_sync(0xFFFFFFFFu, part, 1);
        float score = part * prs;
        float2 vv = *(const float2*)&g_vnode[(size_t)sp*64 + lane*2];
        if (score > m) {
            float c = __expf(m - score);
            s *= c;
            #pragma unroll
            for (int rr = 0; rr < 8; rr++) { b[rr].x *= c; b[rr].y *= c; }
            m = score;
        }
        float w = __expf(score - m);
        s += w;
        #pragma unroll
        for (int rr = 0; rr < 8; rr++) if (r == rr) { b[rr].x += w*vv.x; b[rr].y += w*vv.y; }
    }
    float inv = 1.0f / (s + 1e-16f);
    #pragma unroll
    for (int r = 0; r < 8; r++)
        *(float2*)&g_bucket[(size_t)d*512 + r*64 + lane*2] = make_float2(b[r].x*inv, b[r].y*inv);
}

// ---------------- output GEMM: out[node] = bucket[pos][512] @ Wma[t] * sigmoid(skip[t]) ----------------
__global__ void k_out(float* __restrict__ out, const float* __restrict__ skip, const void* nt) {
    extern __shared__ float sm[];
    float* sA = sm;            // 64*128 (bucket chunk, transposed)
    float* sW = sA + 8192;     // 64*64
    int* sNode = (int*)(sW + 4096);
    int* sTy   = sNode + 128;
    int tid = threadIdx.x;
    int base = blockIdx.x * 128;
    if (tid < 128) {
        int idx = base + tid; if (idx > NN-1) idx = NN-1;
        int node = g_perm[idx];
        sNode[tid] = node;
        sTy[tid] = ld_idx(nt, node, g_is64_nt);
    }
    __syncthreads();
    int t0 = sTy[0], t1 = sTy[127];
    int wy = tid >> 4, wx = tid & 15;
    int m0 = wy*8, c0 = wx*4;
    int mload = tid >> 1, half = tid & 1;
    int posl = base + mload; if (posl > NN-1) posl = NN-1;
    for (int t = t0; t <= t1; t++) {
        float acc[8][4];
        #pragma unroll
        for (int i = 0; i < 8; i++)
            #pragma unroll
            for (int j = 0; j < 4; j++) acc[i][j] = 0.f;
        for (int kk = 0; kk < 8; kk++) {
            {
                const float4* bp = (const float4*)&g_bucket[(size_t)posl*512 + kk*64 + half*32];
                #pragma unroll
                for (int j = 0; j < 8; j++) {
                    float4 v = bp[j];
                    int k0 = half*32 + j*4;
                    sA[(k0+0)*128 + mload] = v.x;
                    sA[(k0+1)*128 + mload] = v.y;
                    sA[(k0+2)*128 + mload] = v.z;
                    sA[(k0+3)*128 + mload] = v.w;
                }
            }
            for (int e = tid; e < 1024; e += 256)
                ((float4*)sW)[e] = ((const float4*)&g_Wma[t*32768 + kk*4096])[e];
            __syncthreads();
            #pragma unroll 4
            for (int k = 0; k < 64; k++) {
                float4 bw = *(const float4*)&sW[k*64 + c0];
                float4 a0 = *(const float4*)&sA[k*128 + m0];
                float4 a1 = *(const float4*)&sA[k*128 + m0 + 4];
                float av[8] = {a0.x,a0.y,a0.z,a0.w,a1.x,a1.y,a1.z,a1.w};
                #pragma unroll
                for (int i = 0; i < 8; i++) {
                    acc[i][0] += av[i]*bw.x; acc[i][1] += av[i]*bw.y;
                    acc[i][2] += av[i]*bw.z; acc[i][3] += av[i]*bw.w;
                }
            }
            __syncthreads();
        }
        float sc = 1.0f / (1.0f + __expf(-skip[t]));
        #pragma unroll
        for (int i = 0; i < 8; i++) {
            int row = m0 + i, idx = base + row;
            if (idx < NN && sTy[row] == t) {
                *(float4*)&out[(size_t)sNode[row]*64 + c0] =
                    make_float4(acc[i][0]*sc, acc[i][1]*sc, acc[i][2]*sc, acc[i][3]*sc);
            }
        }
    }
}

// ---------------- launch ----------------
extern "C" void kernel_launch(void* const* d_in, const int* in_sizes, int n_in,
                              void* d_out, int out_size) {
    const float* h   = (const float*)d_in[0];
    const void*  adj = d_in[1];
    const void*  et  = d_in[2];
    const void*  nt  = d_in[3];
    int off = n_in - 8;
    const float* kw   = (const float*)d_in[off + 0];
    const float* qw   = (const float*)d_in[off + 1];
    const float* vw   = (const float*)d_in[off + 2];
    const float* aw   = (const float*)d_in[off + 3];
    const float* pri  = (const float*)d_in[off + 4];
    const float* att  = (const float*)d_in[off + 5];
    const float* msg  = (const float*)d_in[off + 6];
    const float* skip = (const float*)d_in[off + 7];
    float* out = (float*)d_out;

    const int SM_KV   = (8192 + 4096 + 4096)*4 + 256*4 + 16;
    const int SM_QREL = (8192 + 8192)*4 + 256*4 + 16;
    const int SM_OUT  = (8192 + 4096)*4 + 256*4 + 16;
    cudaFuncSetAttribute(k_kv,   cudaFuncAttributeMaxDynamicSharedMemorySize, SM_KV);
    cudaFuncSetAttribute(k_qrel, cudaFuncAttributeMaxDynamicSharedMemorySize, SM_QREL);
    cudaFuncSetAttribute(k_out,  cudaFuncAttributeMaxDynamicSharedMemorySize, SM_OUT);

    k_detect<<<1, 1>>>(adj, et, nt);
    k_zero<<<(NN + 255)/256, 256>>>();
    k_nhist<<<(NN + 255)/256, 256>>>(nt);
    k_tscan<<<1, 1>>>();
    k_nscatter<<<(NN + 255)/256, 256>>>(nt);
    k_iperm<<<(NN + 255)/256, 256>>>();
    k_ehist<<<(EE + 255)/256, 256>>>(adj);
    k_scanA<<<NB_SCAN, 256>>>();
    k_scanB<<<1, 256>>>();
    k_scanC<<<NB_SCAN, 256>>>();
    k_escatter<<<(EE + 255)/256, 256>>>(adj, et);
    k_fold_qa<<<64, 256>>>(qw, att);
    k_fold_ma<<<64, 256>>>(msg, aw);

    int nb = (NN + 127) / 128;
    k_kv<<<nb, 256, SM_KV>>>(h, kw, vw, nt);
    dim3 gq(nb, 4);
    k_qrel<<<gq, 256, SM_QREL>>>(h, nt);
    k_edge<<<(NN + 7)/8, 256>>>(pri);
    k_out<<<nb, 256, SM_OUT>>>(out, skip, nt);
}